// round 3
// baseline (speedup 1.0000x reference)
#include <cuda_runtime.h>
#include <cuda_bf16.h>
#include <math.h>

#define NN   50000
#define EE   800000
#define HID  128
#define OUTD 40

// -------------------- scratch (device globals; no allocs allowed) ------------
__device__ float g_xl[NN * HID];
__device__ float g_xr[NN * HID];
__device__ float g_id[NN * HID];
__device__ float g_x1[NN * HID];
__device__ float g_x2[NN * HID];
__device__ int   g_off[NN + 1];
__device__ int   g_cur[NN];
__device__ int   g_srcs[EE];

// -------------------- small utility kernels (graph-safe; no memset/memcpy) ---
__global__ void zero_int_kernel(int* __restrict__ p, int n) {
    int i = blockIdx.x * blockDim.x + threadIdx.x;
    if (i < n) p[i] = 0;
}
__global__ void copy_int_kernel(const int* __restrict__ s, int* __restrict__ d, int n) {
    int i = blockIdx.x * blockDim.x + threadIdx.x;
    if (i < n) d[i] = s[i];
}

// -------------------- CSR build ----------------------------------------------
__global__ void hist_kernel(const int* __restrict__ ei, int E, int* __restrict__ deg) {
    for (int e = blockIdx.x * blockDim.x + threadIdx.x; e < E; e += gridDim.x * blockDim.x) {
        int d = ei[E + e];
        if ((unsigned)d < (unsigned)NN) atomicAdd(&deg[d], 1);
    }
}

// single-block exclusive scan (warp-shfl based)
__global__ void scan_kernel(const int* __restrict__ deg, int* __restrict__ off, int n) {
    __shared__ int ssum[32];
    __shared__ int scarry;
    int tid = threadIdx.x, lane = tid & 31, wid = tid >> 5;
    if (tid == 0) scarry = 0;
    __syncthreads();
    for (int base = 0; base < n; base += 1024) {
        int idx = base + tid;
        int v = (idx < n) ? deg[idx] : 0;
        int val = v;
#pragma unroll
        for (int s = 1; s < 32; s <<= 1) {
            int t = __shfl_up_sync(0xffffffffu, val, s);
            if (lane >= s) val += t;
        }
        if (lane == 31) ssum[wid] = val;
        __syncthreads();
        if (wid == 0) {
            int w = ssum[lane];
#pragma unroll
            for (int s = 1; s < 32; s <<= 1) {
                int t = __shfl_up_sync(0xffffffffu, w, s);
                if (lane >= s) w += t;
            }
            ssum[lane] = w;
        }
        __syncthreads();
        int blockincl = val + (wid > 0 ? ssum[wid - 1] : 0);
        int c = scarry;
        if (idx < n) off[idx] = c + blockincl - v;
        int total = ssum[31];
        __syncthreads();
        if (tid == 0) scarry = c + total;
        __syncthreads();
    }
    if (threadIdx.x == 0) off[n] = scarry;
}

__global__ void scatter_kernel(const int* __restrict__ ei, int E,
                               int* __restrict__ cur, int* __restrict__ srcs) {
    for (int e = blockIdx.x * blockDim.x + threadIdx.x; e < E; e += gridDim.x * blockDim.x) {
        int d = ei[E + e];
        if ((unsigned)d < (unsigned)NN) {
            int p = atomicAdd(&cur[d], 1);
            if ((unsigned)p < (unsigned)EE) srcs[p] = ei[e];
        }
    }
}

// -------------------- GEMM: C[n,ncols] = A[n,128] @ W[128,ncols] + b ---------
__global__ void gemm_bias_kernel(const float* __restrict__ A, const float* __restrict__ W,
                                 const float* __restrict__ b, float* __restrict__ C,
                                 int n, int ncols) {
    __shared__ float shA[128 * 8];   // layout [k][r]
    int row0 = blockIdx.x * 8;
    int tid = threadIdx.x;           // 128 threads
#pragma unroll
    for (int r = 0; r < 8; r++) {
        int row = row0 + r;
        float v = (row < n) ? A[(size_t)row * 128 + tid] : 0.f;
        shA[tid * 8 + r] = v;
    }
    __syncthreads();
    if (tid < ncols) {
        float acc0 = 0, acc1 = 0, acc2 = 0, acc3 = 0, acc4 = 0, acc5 = 0, acc6 = 0, acc7 = 0;
#pragma unroll 16
        for (int k = 0; k < 128; k++) {
            float wv = __ldg(&W[k * ncols + tid]);
            float4 lo = *(const float4*)&shA[k * 8];
            float4 hi = *(const float4*)&shA[k * 8 + 4];
            acc0 = fmaf(lo.x, wv, acc0);
            acc1 = fmaf(lo.y, wv, acc1);
            acc2 = fmaf(lo.z, wv, acc2);
            acc3 = fmaf(lo.w, wv, acc3);
            acc4 = fmaf(hi.x, wv, acc4);
            acc5 = fmaf(hi.y, wv, acc5);
            acc6 = fmaf(hi.z, wv, acc6);
            acc7 = fmaf(hi.w, wv, acc7);
        }
        float bv = __ldg(&b[tid]);
        float accs[8] = {acc0, acc1, acc2, acc3, acc4, acc5, acc6, acc7};
#pragma unroll
        for (int r = 0; r < 8; r++) {
            int row = row0 + r;
            if (row < n) C[(size_t)row * ncols + tid] = accs[r] + bv;
        }
    }
}

// -------------------- GATv2 per-node kernel (HID=128, H=4, C=32) -------------
// one warp per dst node; lane handles cols [4*lane, 4*lane+4); head = lane>>3.
// fused: softmax (2-pass, recompute), bias, layernorm, gelu(exact), residual.
__global__ void gat_node128_kernel(const float* __restrict__ xl, const float* __restrict__ xr,
                                   const int* __restrict__ off, const int* __restrict__ srcs,
                                   const float* __restrict__ att, const float* __restrict__ bias,
                                   const float* __restrict__ gamma, const float* __restrict__ beta,
                                   const float* __restrict__ resid, float* __restrict__ out, int n) {
    int warp = (blockIdx.x * blockDim.x + threadIdx.x) >> 5;
    if (warp >= n) return;
    int lane = threadIdx.x & 31;
    int c0 = lane * 4;
    const float4 xrv = *(const float4*)&xr[(size_t)warp * 128 + c0];
    const float4 attv = *(const float4*)&att[c0];
    int beg = __ldg(&off[warp]), end = __ldg(&off[warp + 1]);

    // pass 1: per-head max of alpha
    float mh = -3.4e38f;
    for (int i = beg; i < end; i++) {
        int s = __ldg(&srcs[i]);
        float4 xv = *(const float4*)&xl[(size_t)s * 128 + c0];
        float e0 = xv.x + xrv.x; e0 = fmaxf(e0, 0.2f * e0);
        float e1 = xv.y + xrv.y; e1 = fmaxf(e1, 0.2f * e1);
        float e2 = xv.z + xrv.z; e2 = fmaxf(e2, 0.2f * e2);
        float e3 = xv.w + xrv.w; e3 = fmaxf(e3, 0.2f * e3);
        float p = e0 * attv.x + e1 * attv.y + e2 * attv.z + e3 * attv.w;
        p += __shfl_xor_sync(0xffffffffu, p, 1);
        p += __shfl_xor_sync(0xffffffffu, p, 2);
        p += __shfl_xor_sync(0xffffffffu, p, 4);
        mh = fmaxf(mh, p);
    }

    // pass 2: weighted sum (denominator factored out)
    float sw = 0.f;
    float a0 = 0, a1 = 0, a2 = 0, a3 = 0;
    for (int i = beg; i < end; i++) {
        int s = __ldg(&srcs[i]);
        float4 xv = *(const float4*)&xl[(size_t)s * 128 + c0];
        float e0 = xv.x + xrv.x; e0 = fmaxf(e0, 0.2f * e0);
        float e1 = xv.y + xrv.y; e1 = fmaxf(e1, 0.2f * e1);
        float e2 = xv.z + xrv.z; e2 = fmaxf(e2, 0.2f * e2);
        float e3 = xv.w + xrv.w; e3 = fmaxf(e3, 0.2f * e3);
        float p = e0 * attv.x + e1 * attv.y + e2 * attv.z + e3 * attv.w;
        p += __shfl_xor_sync(0xffffffffu, p, 1);
        p += __shfl_xor_sync(0xffffffffu, p, 2);
        p += __shfl_xor_sync(0xffffffffu, p, 4);
        float w = __expf(p - mh);
        sw += w;
        a0 = fmaf(w, xv.x, a0);
        a1 = fmaf(w, xv.y, a1);
        a2 = fmaf(w, xv.z, a2);
        a3 = fmaf(w, xv.w, a3);
    }
    float inv = 1.f / (sw + 1e-16f);
    const float4 bv = *(const float4*)&bias[c0];
    float o0 = a0 * inv + bv.x;
    float o1 = a1 * inv + bv.y;
    float o2 = a2 * inv + bv.z;
    float o3 = a3 * inv + bv.w;

    // layernorm over the 128 features (full-warp reduction)
    float s1 = o0 + o1 + o2 + o3;
    float s2 = o0 * o0 + o1 * o1 + o2 * o2 + o3 * o3;
#pragma unroll
    for (int s = 16; s >= 1; s >>= 1) {
        s1 += __shfl_xor_sync(0xffffffffu, s1, s);
        s2 += __shfl_xor_sync(0xffffffffu, s2, s);
    }
    float mu = s1 * (1.f / 128.f);
    float var = s2 * (1.f / 128.f) - mu * mu;
    float rinv = rsqrtf(var + 1e-5f);
    const float4 gv = *(const float4*)&gamma[c0];
    const float4 btv = *(const float4*)&beta[c0];
    const float4 rv = *(const float4*)&resid[(size_t)warp * 128 + c0];

    float y0 = (o0 - mu) * rinv * gv.x + btv.x;
    float y1 = (o1 - mu) * rinv * gv.y + btv.y;
    float y2 = (o2 - mu) * rinv * gv.z + btv.z;
    float y3 = (o3 - mu) * rinv * gv.w + btv.w;
    // exact gelu
    y0 = 0.5f * y0 * (1.f + erff(y0 * 0.70710678118654752f));
    y1 = 0.5f * y1 * (1.f + erff(y1 * 0.70710678118654752f));
    y2 = 0.5f * y2 * (1.f + erff(y2 * 0.70710678118654752f));
    y3 = 0.5f * y3 * (1.f + erff(y3 * 0.70710678118654752f));

    float4 res;
    res.x = y0 + rv.x;
    res.y = y1 + rv.y;
    res.z = y2 + rv.z;
    res.w = y3 + rv.w;
    *(float4*)&out[(size_t)warp * 128 + c0] = res;
}

// -------------------- GATv2 final layer (H=1, C=40) --------------------------
// one warp per node; lane handles col=lane (<40) and col=lane+32 (lane<8)
__global__ void gat_node40_kernel(const float* __restrict__ xl, const float* __restrict__ xr,
                                  const int* __restrict__ off, const int* __restrict__ srcs,
                                  const float* __restrict__ att, const float* __restrict__ bias,
                                  float* __restrict__ out, int n) {
    int warp = (blockIdx.x * blockDim.x + threadIdx.x) >> 5;
    if (warp >= n) return;
    int lane = threadIdx.x & 31;
    bool has2 = lane < 8;
    float xr0 = xr[(size_t)warp * 40 + lane];
    float xr1 = has2 ? xr[(size_t)warp * 40 + 32 + lane] : 0.f;
    float at0 = (lane < 32) ? __ldg(&att[lane]) : 0.f;
    float at1 = has2 ? __ldg(&att[32 + lane]) : 0.f;
    int beg = __ldg(&off[warp]), end = __ldg(&off[warp + 1]);

    float mh = -3.4e38f;
    for (int i = beg; i < end; i++) {
        int s = __ldg(&srcs[i]);
        float x0 = xl[(size_t)s * 40 + lane];
        float x1 = has2 ? xl[(size_t)s * 40 + 32 + lane] : 0.f;
        float e0 = x0 + xr0; e0 = fmaxf(e0, 0.2f * e0);
        float e1 = x1 + xr1; e1 = fmaxf(e1, 0.2f * e1);
        float p = e0 * at0 + e1 * at1;
#pragma unroll
        for (int s2 = 16; s2 >= 1; s2 >>= 1) p += __shfl_xor_sync(0xffffffffu, p, s2);
        mh = fmaxf(mh, p);
    }
    float sw = 0.f, acc0 = 0.f, acc1 = 0.f;
    for (int i = beg; i < end; i++) {
        int s = __ldg(&srcs[i]);
        float x0 = xl[(size_t)s * 40 + lane];
        float x1 = has2 ? xl[(size_t)s * 40 + 32 + lane] : 0.f;
        float e0 = x0 + xr0; e0 = fmaxf(e0, 0.2f * e0);
        float e1 = x1 + xr1; e1 = fmaxf(e1, 0.2f * e1);
        float p = e0 * at0 + e1 * at1;
#pragma unroll
        for (int s2 = 16; s2 >= 1; s2 >>= 1) p += __shfl_xor_sync(0xffffffffu, p, s2);
        float w = __expf(p - mh);
        sw += w;
        acc0 = fmaf(w, x0, acc0);
        acc1 = fmaf(w, x1, acc1);
    }
    float inv = 1.f / (sw + 1e-16f);
    out[(size_t)warp * 40 + lane] = acc0 * inv + __ldg(&bias[lane]);
    if (has2) out[(size_t)warp * 40 + 32 + lane] = acc1 * inv + __ldg(&bias[32 + lane]);
}

// -------------------- launch --------------------------------------------------
extern "C" void kernel_launch(void* const* d_in, const int* in_sizes, int n_in,
                              void* d_out, int out_size) {
    const float* x     = (const float*)d_in[0];
    const int*   ei    = (const int*)d_in[1];   // edge_index delivered as int32, shape (2,E)
    const float* W0   = (const float*)d_in[2];  const float* b0   = (const float*)d_in[3];
    const float* W1l  = (const float*)d_in[4];  const float* b1l  = (const float*)d_in[5];
    const float* W1r  = (const float*)d_in[6];  const float* b1r  = (const float*)d_in[7];
    const float* att1 = (const float*)d_in[8];  const float* bias1= (const float*)d_in[9];
    const float* g1   = (const float*)d_in[10]; const float* be1  = (const float*)d_in[11];
    const float* W2l  = (const float*)d_in[12]; const float* b2l  = (const float*)d_in[13];
    const float* W2r  = (const float*)d_in[14]; const float* b2r  = (const float*)d_in[15];
    const float* att2 = (const float*)d_in[16]; const float* bias2= (const float*)d_in[17];
    const float* g2   = (const float*)d_in[18]; const float* be2  = (const float*)d_in[19];
    const float* W3l  = (const float*)d_in[20]; const float* b3l  = (const float*)d_in[21];
    const float* W3r  = (const float*)d_in[22]; const float* b3r  = (const float*)d_in[23];
    const float* att3 = (const float*)d_in[24]; const float* bias3= (const float*)d_in[25];
    float* out = (float*)d_out;

    float *xl, *xr, *idn, *x1, *x2;
    int *off, *cur, *srcs;
    cudaGetSymbolAddress((void**)&xl,   g_xl);
    cudaGetSymbolAddress((void**)&xr,   g_xr);
    cudaGetSymbolAddress((void**)&idn,  g_id);
    cudaGetSymbolAddress((void**)&x1,   g_x1);
    cudaGetSymbolAddress((void**)&x2,   g_x2);
    cudaGetSymbolAddress((void**)&off,  g_off);
    cudaGetSymbolAddress((void**)&cur,  g_cur);
    cudaGetSymbolAddress((void**)&srcs, g_srcs);

    const int N = NN, E = EE;
    int eblocks = (E + 255) / 256;
    int gblocks = (N + 7) / 8;
    int nblocks = (N + 255) / 256;

    // ---- CSR build (deg in cur -> scan -> off; cur <- off; scatter) ----
    zero_int_kernel<<<nblocks, 256>>>(cur, N);
    hist_kernel<<<eblocks, 256>>>(ei, E, cur);
    scan_kernel<<<1, 1024>>>(cur, off, N);
    copy_int_kernel<<<nblocks, 256>>>(off, cur, N);
    scatter_kernel<<<eblocks, 256>>>(ei, E, cur, srcs);

    // ---- identity + layer 1 ----
    gemm_bias_kernel<<<gblocks, 128>>>(x, W0, b0, idn, N, HID);
    gemm_bias_kernel<<<gblocks, 128>>>(x, W1l, b1l, xl, N, HID);
    gemm_bias_kernel<<<gblocks, 128>>>(x, W1r, b1r, xr, N, HID);
    gat_node128_kernel<<<gblocks, 256>>>(xl, xr, off, srcs, att1, bias1, g1, be1, idn, x1, N);

    // ---- layer 2 ----
    gemm_bias_kernel<<<gblocks, 128>>>(x1, W2l, b2l, xl, N, HID);
    gemm_bias_kernel<<<gblocks, 128>>>(x1, W2r, b2r, xr, N, HID);
    gat_node128_kernel<<<gblocks, 256>>>(xl, xr, off, srcs, att2, bias2, g2, be2, x1, x2, N);

    // ---- layer 3 ----
    gemm_bias_kernel<<<gblocks, 128>>>(x2, W3l, b3l, xl, N, OUTD);
    gemm_bias_kernel<<<gblocks, 128>>>(x2, W3r, b3r, xr, N, OUTD);
    gat_node40_kernel<<<gblocks, 256>>>(xl, xr, off, srcs, att3, bias3, out, N);
}

// round 4
// speedup vs baseline: 1.3021x; 1.3021x over previous
#include <cuda_runtime.h>
#include <cuda_bf16.h>
#include <math.h>

#define NN   50000
#define EE   800000
#define HID  128
#define OUTD 40

// -------------------- scratch (device globals; no allocs allowed) ------------
__device__ float g_xl[NN * HID];
__device__ float g_xr[NN * HID];
__device__ float g_id[NN * HID];
__device__ float g_x1[NN * HID];
__device__ float g_x2[NN * HID];
__device__ int   g_off[NN + 1];
__device__ int   g_cur[NN];
__device__ int   g_srcs[EE];

// -------------------- small utility kernels ----------------------------------
__global__ void zero_int_kernel(int* __restrict__ p, int n) {
    int i = blockIdx.x * blockDim.x + threadIdx.x;
    if (i < n) p[i] = 0;
}
__global__ void copy_int_kernel(const int* __restrict__ s, int* __restrict__ d, int n) {
    int i = blockIdx.x * blockDim.x + threadIdx.x;
    if (i < n) d[i] = s[i];
}

// -------------------- CSR build ----------------------------------------------
__global__ void hist_kernel(const int* __restrict__ ei, int E, int* __restrict__ deg) {
    for (int e = blockIdx.x * blockDim.x + threadIdx.x; e < E; e += gridDim.x * blockDim.x) {
        int d = ei[E + e];
        if ((unsigned)d < (unsigned)NN) atomicAdd(&deg[d], 1);
    }
}

__global__ void scan_kernel(const int* __restrict__ deg, int* __restrict__ off, int n) {
    __shared__ int ssum[32];
    __shared__ int scarry;
    int tid = threadIdx.x, lane = tid & 31, wid = tid >> 5;
    if (tid == 0) scarry = 0;
    __syncthreads();
    for (int base = 0; base < n; base += 1024) {
        int idx = base + tid;
        int v = (idx < n) ? deg[idx] : 0;
        int val = v;
#pragma unroll
        for (int s = 1; s < 32; s <<= 1) {
            int t = __shfl_up_sync(0xffffffffu, val, s);
            if (lane >= s) val += t;
        }
        if (lane == 31) ssum[wid] = val;
        __syncthreads();
        if (wid == 0) {
            int w = ssum[lane];
#pragma unroll
            for (int s = 1; s < 32; s <<= 1) {
                int t = __shfl_up_sync(0xffffffffu, w, s);
                if (lane >= s) w += t;
            }
            ssum[lane] = w;
        }
        __syncthreads();
        int blockincl = val + (wid > 0 ? ssum[wid - 1] : 0);
        int c = scarry;
        if (idx < n) off[idx] = c + blockincl - v;
        int total = ssum[31];
        __syncthreads();
        if (tid == 0) scarry = c + total;
        __syncthreads();
    }
    if (threadIdx.x == 0) off[n] = scarry;
}

__global__ void scatter_kernel(const int* __restrict__ ei, int E,
                               int* __restrict__ cur, int* __restrict__ srcs) {
    for (int e = blockIdx.x * blockDim.x + threadIdx.x; e < E; e += gridDim.x * blockDim.x) {
        int d = ei[E + e];
        if ((unsigned)d < (unsigned)NN) {
            int p = atomicAdd(&cur[d], 1);
            if ((unsigned)p < (unsigned)EE) srcs[p] = ei[e];
        }
    }
}

// -------------------- tiled SGEMM: C[n,128] = A[n,128] @ W[128,128] + b ------
// 64x128 block tile, 256 threads, 8x4 accumulators per thread, K-chunks of 16.
__global__ __launch_bounds__(256) void gemm128_kernel(
        const float* __restrict__ A, const float* __restrict__ W,
        const float* __restrict__ b, float* __restrict__ C, int n) {
    __shared__ float As[16][64];
    __shared__ float Ws[16][128];
    int t = threadIdx.x;                 // 256
    int row0 = blockIdx.x * 64;
    float acc[8][4];
#pragma unroll
    for (int i = 0; i < 8; i++)
#pragma unroll
        for (int j = 0; j < 4; j++) acc[i][j] = 0.f;

    int rbase = (t >> 5) * 8;            // warp-uniform
    int cbase = (t & 31) * 4;
    int ar = t >> 2, aseg = (t & 3) * 4; // A-load mapping

    for (int k0 = 0; k0 < 128; k0 += 16) {
        // stage A (64 x 16)
        int arow = row0 + ar;
        float4 av = (arow < n) ? *(const float4*)&A[(size_t)arow * 128 + k0 + aseg]
                               : make_float4(0.f, 0.f, 0.f, 0.f);
        As[aseg + 0][ar] = av.x;
        As[aseg + 1][ar] = av.y;
        As[aseg + 2][ar] = av.z;
        As[aseg + 3][ar] = av.w;
        // stage W (16 x 128)
#pragma unroll
        for (int h = 0; h < 2; h++) {
            int idx = t + h * 256;
            int kk = idx >> 5, c = (idx & 31) * 4;
            *(float4*)&Ws[kk][c] = *(const float4*)&W[(size_t)(k0 + kk) * 128 + c];
        }
        __syncthreads();
#pragma unroll
        for (int kk = 0; kk < 16; kk++) {
            float4 a0 = *(float4*)&As[kk][rbase];
            float4 a1 = *(float4*)&As[kk][rbase + 4];
            float4 wv = *(float4*)&Ws[kk][cbase];
            float arr[8] = {a0.x, a0.y, a0.z, a0.w, a1.x, a1.y, a1.z, a1.w};
            float wr[4]  = {wv.x, wv.y, wv.z, wv.w};
#pragma unroll
            for (int i = 0; i < 8; i++)
#pragma unroll
                for (int j = 0; j < 4; j++)
                    acc[i][j] = fmaf(arr[i], wr[j], acc[i][j]);
        }
        __syncthreads();
    }
    float4 bv = *(const float4*)&b[cbase];
#pragma unroll
    for (int i = 0; i < 8; i++) {
        int row = row0 + rbase + i;
        if (row < n) {
            float4 o;
            o.x = acc[i][0] + bv.x;
            o.y = acc[i][1] + bv.y;
            o.z = acc[i][2] + bv.z;
            o.w = acc[i][3] + bv.w;
            *(float4*)&C[(size_t)row * 128 + cbase] = o;
        }
    }
}

// -------------------- narrow GEMM: C[n,ncols] = A[n,128] @ W + b (ncols<=128) -
__global__ void gemm_bias_kernel(const float* __restrict__ A, const float* __restrict__ W,
                                 const float* __restrict__ b, float* __restrict__ C,
                                 int n, int ncols) {
    __shared__ float shA[128 * 8];   // [k][r]
    int row0 = blockIdx.x * 8;
    int tid = threadIdx.x;           // 128 threads
#pragma unroll
    for (int r = 0; r < 8; r++) {
        int row = row0 + r;
        float v = (row < n) ? A[(size_t)row * 128 + tid] : 0.f;
        shA[tid * 8 + r] = v;
    }
    __syncthreads();
    if (tid < ncols) {
        float acc0 = 0, acc1 = 0, acc2 = 0, acc3 = 0, acc4 = 0, acc5 = 0, acc6 = 0, acc7 = 0;
#pragma unroll 16
        for (int k = 0; k < 128; k++) {
            float wv = __ldg(&W[k * ncols + tid]);
            float4 lo = *(const float4*)&shA[k * 8];
            float4 hi = *(const float4*)&shA[k * 8 + 4];
            acc0 = fmaf(lo.x, wv, acc0);
            acc1 = fmaf(lo.y, wv, acc1);
            acc2 = fmaf(lo.z, wv, acc2);
            acc3 = fmaf(lo.w, wv, acc3);
            acc4 = fmaf(hi.x, wv, acc4);
            acc5 = fmaf(hi.y, wv, acc5);
            acc6 = fmaf(hi.z, wv, acc6);
            acc7 = fmaf(hi.w, wv, acc7);
        }
        float bv = __ldg(&b[tid]);
        float accs[8] = {acc0, acc1, acc2, acc3, acc4, acc5, acc6, acc7};
#pragma unroll
        for (int r = 0; r < 8; r++) {
            int row = row0 + r;
            if (row < n) C[(size_t)row * ncols + tid] = accs[r] + bv;
        }
    }
}

// -------------------- GATv2 per-node kernel (HID=128, H=4, C=32) -------------
// one warp per dst node; lane handles cols [4*lane, 4*lane+4); head = lane>>3.
// ONLINE softmax (single pass) + bias + layernorm + exact gelu + residual.
__global__ void gat_node128_kernel(const float* __restrict__ xl, const float* __restrict__ xr,
                                   const int* __restrict__ off, const int* __restrict__ srcs,
                                   const float* __restrict__ att, const float* __restrict__ bias,
                                   const float* __restrict__ gamma, const float* __restrict__ beta,
                                   const float* __restrict__ resid, float* __restrict__ out, int n) {
    int warp = (blockIdx.x * blockDim.x + threadIdx.x) >> 5;
    if (warp >= n) return;
    int lane = threadIdx.x & 31;
    int c0 = lane * 4;
    const float4 xrv = *(const float4*)&xr[(size_t)warp * 128 + c0];
    const float4 attv = *(const float4*)&att[c0];
    int beg = __ldg(&off[warp]), end = __ldg(&off[warp + 1]);

    float mh = -3.4e38f, sw = 0.f;
    float a0 = 0.f, a1 = 0.f, a2 = 0.f, a3 = 0.f;
    for (int i = beg; i < end; i++) {
        int s = __ldg(&srcs[i]);
        float4 xv = *(const float4*)&xl[(size_t)s * 128 + c0];
        float e0 = xv.x + xrv.x; e0 = fmaxf(e0, 0.2f * e0);
        float e1 = xv.y + xrv.y; e1 = fmaxf(e1, 0.2f * e1);
        float e2 = xv.z + xrv.z; e2 = fmaxf(e2, 0.2f * e2);
        float e3 = xv.w + xrv.w; e3 = fmaxf(e3, 0.2f * e3);
        float p = e0 * attv.x + e1 * attv.y + e2 * attv.z + e3 * attv.w;
        p += __shfl_xor_sync(0xffffffffu, p, 1);
        p += __shfl_xor_sync(0xffffffffu, p, 2);
        p += __shfl_xor_sync(0xffffffffu, p, 4);     // per-head alpha
        if (p > mh) {
            float sc = __expf(mh - p);               // first iter: exp(-inf)=0
            sw = sw * sc + 1.f;
            a0 = a0 * sc + xv.x;
            a1 = a1 * sc + xv.y;
            a2 = a2 * sc + xv.z;
            a3 = a3 * sc + xv.w;
            mh = p;
        } else {
            float w = __expf(p - mh);
            sw += w;
            a0 = fmaf(w, xv.x, a0);
            a1 = fmaf(w, xv.y, a1);
            a2 = fmaf(w, xv.z, a2);
            a3 = fmaf(w, xv.w, a3);
        }
    }
    float inv = 1.f / (sw + 1e-16f);
    const float4 bv = *(const float4*)&bias[c0];
    float o0 = a0 * inv + bv.x;
    float o1 = a1 * inv + bv.y;
    float o2 = a2 * inv + bv.z;
    float o3 = a3 * inv + bv.w;

    // layernorm over 128 features (full-warp reduction)
    float s1 = o0 + o1 + o2 + o3;
    float s2 = o0 * o0 + o1 * o1 + o2 * o2 + o3 * o3;
#pragma unroll
    for (int s = 16; s >= 1; s >>= 1) {
        s1 += __shfl_xor_sync(0xffffffffu, s1, s);
        s2 += __shfl_xor_sync(0xffffffffu, s2, s);
    }
    float mu = s1 * (1.f / 128.f);
    float var = s2 * (1.f / 128.f) - mu * mu;
    float rinv = rsqrtf(var + 1e-5f);
    const float4 gv = *(const float4*)&gamma[c0];
    const float4 btv = *(const float4*)&beta[c0];
    const float4 rv = *(const float4*)&resid[(size_t)warp * 128 + c0];

    float y0 = (o0 - mu) * rinv * gv.x + btv.x;
    float y1 = (o1 - mu) * rinv * gv.y + btv.y;
    float y2 = (o2 - mu) * rinv * gv.z + btv.z;
    float y3 = (o3 - mu) * rinv * gv.w + btv.w;
    y0 = 0.5f * y0 * (1.f + erff(y0 * 0.70710678118654752f));
    y1 = 0.5f * y1 * (1.f + erff(y1 * 0.70710678118654752f));
    y2 = 0.5f * y2 * (1.f + erff(y2 * 0.70710678118654752f));
    y3 = 0.5f * y3 * (1.f + erff(y3 * 0.70710678118654752f));

    float4 res;
    res.x = y0 + rv.x;
    res.y = y1 + rv.y;
    res.z = y2 + rv.z;
    res.w = y3 + rv.w;
    *(float4*)&out[(size_t)warp * 128 + c0] = res;
}

// -------------------- GATv2 final layer (H=1, C=40), online softmax ----------
__global__ void gat_node40_kernel(const float* __restrict__ xl, const float* __restrict__ xr,
                                  const int* __restrict__ off, const int* __restrict__ srcs,
                                  const float* __restrict__ att, const float* __restrict__ bias,
                                  float* __restrict__ out, int n) {
    int warp = (blockIdx.x * blockDim.x + threadIdx.x) >> 5;
    if (warp >= n) return;
    int lane = threadIdx.x & 31;
    bool has2 = lane < 8;
    float xr0 = xr[(size_t)warp * 40 + lane];
    float xr1 = has2 ? xr[(size_t)warp * 40 + 32 + lane] : 0.f;
    float at0 = __ldg(&att[lane]);
    float at1 = has2 ? __ldg(&att[32 + lane]) : 0.f;
    int beg = __ldg(&off[warp]), end = __ldg(&off[warp + 1]);

    float mh = -3.4e38f, sw = 0.f, acc0 = 0.f, acc1 = 0.f;
    for (int i = beg; i < end; i++) {
        int s = __ldg(&srcs[i]);
        float x0 = xl[(size_t)s * 40 + lane];
        float x1 = has2 ? xl[(size_t)s * 40 + 32 + lane] : 0.f;
        float e0 = x0 + xr0; e0 = fmaxf(e0, 0.2f * e0);
        float e1 = x1 + xr1; e1 = fmaxf(e1, 0.2f * e1);
        float p = e0 * at0 + e1 * at1;
#pragma unroll
        for (int s2 = 16; s2 >= 1; s2 >>= 1) p += __shfl_xor_sync(0xffffffffu, p, s2);
        if (p > mh) {
            float sc = __expf(mh - p);
            sw = sw * sc + 1.f;
            acc0 = acc0 * sc + x0;
            acc1 = acc1 * sc + x1;
            mh = p;
        } else {
            float w = __expf(p - mh);
            sw += w;
            acc0 = fmaf(w, x0, acc0);
            acc1 = fmaf(w, x1, acc1);
        }
    }
    float inv = 1.f / (sw + 1e-16f);
    out[(size_t)warp * 40 + lane] = acc0 * inv + __ldg(&bias[lane]);
    if (has2) out[(size_t)warp * 40 + 32 + lane] = acc1 * inv + __ldg(&bias[32 + lane]);
}

// -------------------- launch --------------------------------------------------
extern "C" void kernel_launch(void* const* d_in, const int* in_sizes, int n_in,
                              void* d_out, int out_size) {
    const float* x     = (const float*)d_in[0];
    const int*   ei    = (const int*)d_in[1];   // edge_index int32, shape (2,E)
    const float* W0   = (const float*)d_in[2];  const float* b0   = (const float*)d_in[3];
    const float* W1l  = (const float*)d_in[4];  const float* b1l  = (const float*)d_in[5];
    const float* W1r  = (const float*)d_in[6];  const float* b1r  = (const float*)d_in[7];
    const float* att1 = (const float*)d_in[8];  const float* bias1= (const float*)d_in[9];
    const float* g1   = (const float*)d_in[10]; const float* be1  = (const float*)d_in[11];
    const float* W2l  = (const float*)d_in[12]; const float* b2l  = (const float*)d_in[13];
    const float* W2r  = (const float*)d_in[14]; const float* b2r  = (const float*)d_in[15];
    const float* att2 = (const float*)d_in[16]; const float* bias2= (const float*)d_in[17];
    const float* g2   = (const float*)d_in[18]; const float* be2  = (const float*)d_in[19];
    const float* W3l  = (const float*)d_in[20]; const float* b3l  = (const float*)d_in[21];
    const float* W3r  = (const float*)d_in[22]; const float* b3r  = (const float*)d_in[23];
    const float* att3 = (const float*)d_in[24]; const float* bias3= (const float*)d_in[25];
    float* out = (float*)d_out;

    float *xl, *xr, *idn, *x1, *x2;
    int *off, *cur, *srcs;
    cudaGetSymbolAddress((void**)&xl,   g_xl);
    cudaGetSymbolAddress((void**)&xr,   g_xr);
    cudaGetSymbolAddress((void**)&idn,  g_id);
    cudaGetSymbolAddress((void**)&x1,   g_x1);
    cudaGetSymbolAddress((void**)&x2,   g_x2);
    cudaGetSymbolAddress((void**)&off,  g_off);
    cudaGetSymbolAddress((void**)&cur,  g_cur);
    cudaGetSymbolAddress((void**)&srcs, g_srcs);

    const int N = NN, E = EE;
    int eblocks = (E + 255) / 256;
    int gatblocks = (N + 7) / 8;
    int nblocks = (N + 255) / 256;
    int mmblocks = (N + 63) / 64;

    // ---- CSR build ----
    zero_int_kernel<<<nblocks, 256>>>(cur, N);
    hist_kernel<<<eblocks, 256>>>(ei, E, cur);
    scan_kernel<<<1, 1024>>>(cur, off, N);
    copy_int_kernel<<<nblocks, 256>>>(off, cur, N);
    scatter_kernel<<<eblocks, 256>>>(ei, E, cur, srcs);

    // ---- identity + layer 1 ----
    gemm128_kernel<<<mmblocks, 256>>>(x, W0, b0, idn, N);
    gemm128_kernel<<<mmblocks, 256>>>(x, W1l, b1l, xl, N);
    gemm128_kernel<<<mmblocks, 256>>>(x, W1r, b1r, xr, N);
    gat_node128_kernel<<<gatblocks, 256>>>(xl, xr, off, srcs, att1, bias1, g1, be1, idn, x1, N);

    // ---- layer 2 ----
    gemm128_kernel<<<mmblocks, 256>>>(x1, W2l, b2l, xl, N);
    gemm128_kernel<<<mmblocks, 256>>>(x1, W2r, b2r, xr, N);
    gat_node128_kernel<<<gatblocks, 256>>>(xl, xr, off, srcs, att2, bias2, g2, be2, x1, x2, N);

    // ---- layer 3 ----
    gemm_bias_kernel<<<(N + 7) / 8, 128>>>(x2, W3l, b3l, xl, N, OUTD);
    gemm_bias_kernel<<<(N + 7) / 8, 128>>>(x2, W3r, b3r, xr, N, OUTD);
    gat_node40_kernel<<<gatblocks, 256>>>(xl, xr, off, srcs, att3, bias3, out, N);
}

// round 5
// speedup vs baseline: 1.3621x; 1.0461x over previous
#include <cuda_runtime.h>
#include <cuda_bf16.h>
#include <math.h>

#define NN   50000
#define EE   800000
#define HID  128
#define OUTD 40

// -------------------- scratch (device globals; no allocs allowed) ------------
__device__ float g_xl[NN * HID];
__device__ float g_xr[NN * HID];
__device__ float g_id[NN * HID];
__device__ float g_x1[NN * HID];
__device__ float g_x2[NN * HID];
__device__ int   g_off[NN + 1];
__device__ int   g_cur[NN];
__device__ int   g_srcs[EE];

// -------------------- f32x2 packed-FMA helpers -------------------------------
__device__ __forceinline__ unsigned long long pack2(float x, float y) {
    unsigned long long r;
    asm("mov.b64 %0, {%1, %2};" : "=l"(r) : "f"(x), "f"(y));
    return r;
}
__device__ __forceinline__ void unpack2(unsigned long long v, float& x, float& y) {
    asm("mov.b64 {%0, %1}, %2;" : "=f"(x), "=f"(y) : "l"(v));
}
__device__ __forceinline__ void ffma2(unsigned long long& d, unsigned long long a,
                                      unsigned long long b) {
    asm("fma.rn.f32x2 %0, %1, %2, %0;" : "+l"(d) : "l"(a), "l"(b));
}

// -------------------- small utility kernels ----------------------------------
__global__ void zero_int_kernel(int* __restrict__ p, int n) {
    int i = blockIdx.x * blockDim.x + threadIdx.x;
    if (i < n) p[i] = 0;
}
__global__ void copy_int_kernel(const int* __restrict__ s, int* __restrict__ d, int n) {
    int i = blockIdx.x * blockDim.x + threadIdx.x;
    if (i < n) d[i] = s[i];
}

// -------------------- CSR build ----------------------------------------------
__global__ void hist_kernel(const int* __restrict__ ei, int E, int* __restrict__ deg) {
    for (int e = blockIdx.x * blockDim.x + threadIdx.x; e < E; e += gridDim.x * blockDim.x) {
        int d = ei[E + e];
        if ((unsigned)d < (unsigned)NN) atomicAdd(&deg[d], 1);
    }
}

__global__ void scan_kernel(const int* __restrict__ deg, int* __restrict__ off, int n) {
    __shared__ int ssum[32];
    __shared__ int scarry;
    int tid = threadIdx.x, lane = tid & 31, wid = tid >> 5;
    if (tid == 0) scarry = 0;
    __syncthreads();
    for (int base = 0; base < n; base += 1024) {
        int idx = base + tid;
        int v = (idx < n) ? deg[idx] : 0;
        int val = v;
#pragma unroll
        for (int s = 1; s < 32; s <<= 1) {
            int t = __shfl_up_sync(0xffffffffu, val, s);
            if (lane >= s) val += t;
        }
        if (lane == 31) ssum[wid] = val;
        __syncthreads();
        if (wid == 0) {
            int w = ssum[lane];
#pragma unroll
            for (int s = 1; s < 32; s <<= 1) {
                int t = __shfl_up_sync(0xffffffffu, w, s);
                if (lane >= s) w += t;
            }
            ssum[lane] = w;
        }
        __syncthreads();
        int blockincl = val + (wid > 0 ? ssum[wid - 1] : 0);
        int c = scarry;
        if (idx < n) off[idx] = c + blockincl - v;
        int total = ssum[31];
        __syncthreads();
        if (tid == 0) scarry = c + total;
        __syncthreads();
    }
    if (threadIdx.x == 0) off[n] = scarry;
}

__global__ void scatter_kernel(const int* __restrict__ ei, int E,
                               int* __restrict__ cur, int* __restrict__ srcs) {
    for (int e = blockIdx.x * blockDim.x + threadIdx.x; e < E; e += gridDim.x * blockDim.x) {
        int d = ei[E + e];
        if ((unsigned)d < (unsigned)NN) {
            int p = atomicAdd(&cur[d], 1);
            if ((unsigned)p < (unsigned)EE) srcs[p] = ei[e];
        }
    }
}

// -------------------- tiled SGEMM (f32x2): C[n,128] = A[n,128]@W[128,128]+b --
// 64x128 tile, 256 threads, acc = 4 row-pairs x 4 cols (packed f32x2).
__global__ __launch_bounds__(256) void gemm128_kernel(
        const float* __restrict__ A, const float* __restrict__ W,
        const float* __restrict__ b, float* __restrict__ C, int n) {
    __shared__ float As[16][64];
    __shared__ float Ws[16][128];
    int t = threadIdx.x;                 // 256
    int row0 = blockIdx.x * 64;
    unsigned long long acc[4][4];        // [row-pair][col]
#pragma unroll
    for (int i = 0; i < 4; i++)
#pragma unroll
        for (int j = 0; j < 4; j++) acc[i][j] = 0ull;

    int rbase = (t >> 5) * 8;            // warp-uniform, 8 rows per warp
    int cbase = (t & 31) * 4;
    int ar = t >> 2, aseg = (t & 3) * 4; // A-load mapping

    for (int k0 = 0; k0 < 128; k0 += 16) {
        // stage A (64 rows x 16 k), transposed to [k][row]
        int arow = row0 + ar;
        float4 av = (arow < n) ? *(const float4*)&A[(size_t)arow * 128 + k0 + aseg]
                               : make_float4(0.f, 0.f, 0.f, 0.f);
        As[aseg + 0][ar] = av.x;
        As[aseg + 1][ar] = av.y;
        As[aseg + 2][ar] = av.z;
        As[aseg + 3][ar] = av.w;
        // stage W (16 k x 128 cols)
#pragma unroll
        for (int h = 0; h < 2; h++) {
            int idx = t + h * 256;
            int kk = idx >> 5, c = (idx & 31) * 4;
            *(float4*)&Ws[kk][c] = *(const float4*)&W[(size_t)(k0 + kk) * 128 + c];
        }
        __syncthreads();
#pragma unroll
        for (int kk = 0; kk < 16; kk++) {
            // A row-pairs: 8 consecutive rows -> 4 packed f32x2 (natural 64-bit lds)
            ulonglong2 ap01 = *(ulonglong2*)&As[kk][rbase];       // rows 0-3
            ulonglong2 ap23 = *(ulonglong2*)&As[kk][rbase + 4];   // rows 4-7
            float4 wv = *(float4*)&Ws[kk][cbase];
            unsigned long long wd[4];
            wd[0] = pack2(wv.x, wv.x);
            wd[1] = pack2(wv.y, wv.y);
            wd[2] = pack2(wv.z, wv.z);
            wd[3] = pack2(wv.w, wv.w);
            unsigned long long ap[4] = {ap01.x, ap01.y, ap23.x, ap23.y};
#pragma unroll
            for (int i = 0; i < 4; i++)
#pragma unroll
                for (int j = 0; j < 4; j++)
                    ffma2(acc[i][j], ap[i], wd[j]);
        }
        __syncthreads();
    }
    float4 bv = *(const float4*)&b[cbase];
#pragma unroll
    for (int i = 0; i < 4; i++) {
        float lo0, hi0, lo1, hi1, lo2, hi2, lo3, hi3;
        unpack2(acc[i][0], lo0, hi0);
        unpack2(acc[i][1], lo1, hi1);
        unpack2(acc[i][2], lo2, hi2);
        unpack2(acc[i][3], lo3, hi3);
        int rowA = row0 + rbase + 2 * i;
        int rowB = rowA + 1;
        if (rowA < n) {
            float4 o = make_float4(lo0 + bv.x, lo1 + bv.y, lo2 + bv.z, lo3 + bv.w);
            *(float4*)&C[(size_t)rowA * 128 + cbase] = o;
        }
        if (rowB < n) {
            float4 o = make_float4(hi0 + bv.x, hi1 + bv.y, hi2 + bv.z, hi3 + bv.w);
            *(float4*)&C[(size_t)rowB * 128 + cbase] = o;
        }
    }
}

// -------------------- fused narrow GEMM pair: Cl/Cr[n,40] = A[n,128]@Wl/Wr+b -
// 128 threads, 8 rows/block. tid<64 -> Wl col tid; tid>=64 -> Wr col tid-64.
__global__ void gemm40x2_kernel(const float* __restrict__ A,
                                const float* __restrict__ Wl, const float* __restrict__ bl,
                                const float* __restrict__ Wr, const float* __restrict__ br,
                                float* __restrict__ Cl, float* __restrict__ Cr, int n) {
    __shared__ float shA[128 * 8];   // [k][r], r = 8 rows
    int row0 = blockIdx.x * 8;
    int tid = threadIdx.x;           // 128
#pragma unroll
    for (int r = 0; r < 8; r++) {
        int row = row0 + r;
        float v = (row < n) ? A[(size_t)row * 128 + tid] : 0.f;
        shA[tid * 8 + r] = v;
    }
    __syncthreads();
    int c = tid & 63;
    bool right = tid >= 64;
    if (c < OUTD) {
        const float* W = right ? Wr : Wl;
        unsigned long long acc[4] = {0ull, 0ull, 0ull, 0ull};
#pragma unroll 8
        for (int k = 0; k < 128; k++) {
            float wv = __ldg(&W[k * OUTD + c]);
            unsigned long long wd = pack2(wv, wv);
            ulonglong2 a01 = *(ulonglong2*)&shA[k * 8];
            ulonglong2 a23 = *(ulonglong2*)&shA[k * 8 + 4];
            ffma2(acc[0], a01.x, wd);
            ffma2(acc[1], a01.y, wd);
            ffma2(acc[2], a23.x, wd);
            ffma2(acc[3], a23.y, wd);
        }
        float bv = right ? __ldg(&br[c]) : __ldg(&bl[c]);
        float* C = right ? Cr : Cl;
        float v[8];
        unpack2(acc[0], v[0], v[1]);
        unpack2(acc[1], v[2], v[3]);
        unpack2(acc[2], v[4], v[5]);
        unpack2(acc[3], v[6], v[7]);
#pragma unroll
        for (int r = 0; r < 8; r++) {
            int row = row0 + r;
            if (row < n) C[(size_t)row * OUTD + c] = v[r] + bv;
        }
    }
}

// -------------------- GATv2 per-node kernel (HID=128, H=4, C=32) -------------
// one warp per dst node; lane handles cols [4*lane,4*lane+4); head = lane>>3.
// ONLINE softmax + bias + layernorm + exact gelu + residual.
__global__ void gat_node128_kernel(const float* __restrict__ xl, const float* __restrict__ xr,
                                   const int* __restrict__ off, const int* __restrict__ srcs,
                                   const float* __restrict__ att, const float* __restrict__ bias,
                                   const float* __restrict__ gamma, const float* __restrict__ beta,
                                   const float* __restrict__ resid, float* __restrict__ out, int n) {
    int warp = (blockIdx.x * blockDim.x + threadIdx.x) >> 5;
    if (warp >= n) return;
    int lane = threadIdx.x & 31;
    int c0 = lane * 4;
    const float4 xrv = *(const float4*)&xr[(size_t)warp * 128 + c0];
    const float4 attv = *(const float4*)&att[c0];
    int beg = __ldg(&off[warp]), end = __ldg(&off[warp + 1]);

    float mh = -3.4e38f, sw = 0.f;
    float a0 = 0.f, a1 = 0.f, a2 = 0.f, a3 = 0.f;
    for (int i = beg; i < end; i++) {
        int s = __ldg(&srcs[i]);
        float4 xv = *(const float4*)&xl[(size_t)s * 128 + c0];
        float e0 = xv.x + xrv.x; e0 = fmaxf(e0, 0.2f * e0);
        float e1 = xv.y + xrv.y; e1 = fmaxf(e1, 0.2f * e1);
        float e2 = xv.z + xrv.z; e2 = fmaxf(e2, 0.2f * e2);
        float e3 = xv.w + xrv.w; e3 = fmaxf(e3, 0.2f * e3);
        float p = e0 * attv.x + e1 * attv.y + e2 * attv.z + e3 * attv.w;
        p += __shfl_xor_sync(0xffffffffu, p, 1);
        p += __shfl_xor_sync(0xffffffffu, p, 2);
        p += __shfl_xor_sync(0xffffffffu, p, 4);     // per-head alpha
        if (p > mh) {
            float sc = __expf(mh - p);               // first iter: exp(-inf)=0
            sw = sw * sc + 1.f;
            a0 = a0 * sc + xv.x;
            a1 = a1 * sc + xv.y;
            a2 = a2 * sc + xv.z;
            a3 = a3 * sc + xv.w;
            mh = p;
        } else {
            float w = __expf(p - mh);
            sw += w;
            a0 = fmaf(w, xv.x, a0);
            a1 = fmaf(w, xv.y, a1);
            a2 = fmaf(w, xv.z, a2);
            a3 = fmaf(w, xv.w, a3);
        }
    }
    float inv = 1.f / (sw + 1e-16f);
    const float4 bv = *(const float4*)&bias[c0];
    float o0 = a0 * inv + bv.x;
    float o1 = a1 * inv + bv.y;
    float o2 = a2 * inv + bv.z;
    float o3 = a3 * inv + bv.w;

    float s1 = o0 + o1 + o2 + o3;
    float s2 = o0 * o0 + o1 * o1 + o2 * o2 + o3 * o3;
#pragma unroll
    for (int s = 16; s >= 1; s >>= 1) {
        s1 += __shfl_xor_sync(0xffffffffu, s1, s);
        s2 += __shfl_xor_sync(0xffffffffu, s2, s);
    }
    float mu = s1 * (1.f / 128.f);
    float var = s2 * (1.f / 128.f) - mu * mu;
    float rinv = rsqrtf(var + 1e-5f);
    const float4 gv = *(const float4*)&gamma[c0];
    const float4 btv = *(const float4*)&beta[c0];
    const float4 rv = *(const float4*)&resid[(size_t)warp * 128 + c0];

    float y0 = (o0 - mu) * rinv * gv.x + btv.x;
    float y1 = (o1 - mu) * rinv * gv.y + btv.y;
    float y2 = (o2 - mu) * rinv * gv.z + btv.z;
    float y3 = (o3 - mu) * rinv * gv.w + btv.w;
    y0 = 0.5f * y0 * (1.f + erff(y0 * 0.70710678118654752f));
    y1 = 0.5f * y1 * (1.f + erff(y1 * 0.70710678118654752f));
    y2 = 0.5f * y2 * (1.f + erff(y2 * 0.70710678118654752f));
    y3 = 0.5f * y3 * (1.f + erff(y3 * 0.70710678118654752f));

    float4 res;
    res.x = y0 + rv.x;
    res.y = y1 + rv.y;
    res.z = y2 + rv.z;
    res.w = y3 + rv.w;
    *(float4*)&out[(size_t)warp * 128 + c0] = res;
}

// -------------------- GATv2 final layer (H=1, C=40), online softmax ----------
__global__ void gat_node40_kernel(const float* __restrict__ xl, const float* __restrict__ xr,
                                  const int* __restrict__ off, const int* __restrict__ srcs,
                                  const float* __restrict__ att, const float* __restrict__ bias,
                                  float* __restrict__ out, int n) {
    int warp = (blockIdx.x * blockDim.x + threadIdx.x) >> 5;
    if (warp >= n) return;
    int lane = threadIdx.x & 31;
    bool has2 = lane < 8;
    float xr0 = xr[(size_t)warp * 40 + lane];
    float xr1 = has2 ? xr[(size_t)warp * 40 + 32 + lane] : 0.f;
    float at0 = __ldg(&att[lane]);
    float at1 = has2 ? __ldg(&att[32 + lane]) : 0.f;
    int beg = __ldg(&off[warp]), end = __ldg(&off[warp + 1]);

    float mh = -3.4e38f, sw = 0.f, acc0 = 0.f, acc1 = 0.f;
    for (int i = beg; i < end; i++) {
        int s = __ldg(&srcs[i]);
        float x0 = xl[(size_t)s * 40 + lane];
        float x1 = has2 ? xl[(size_t)s * 40 + 32 + lane] : 0.f;
        float e0 = x0 + xr0; e0 = fmaxf(e0, 0.2f * e0);
        float e1 = x1 + xr1; e1 = fmaxf(e1, 0.2f * e1);
        float p = e0 * at0 + e1 * at1;
#pragma unroll
        for (int s2 = 16; s2 >= 1; s2 >>= 1) p += __shfl_xor_sync(0xffffffffu, p, s2);
        if (p > mh) {
            float sc = __expf(mh - p);
            sw = sw * sc + 1.f;
            acc0 = acc0 * sc + x0;
            acc1 = acc1 * sc + x1;
            mh = p;
        } else {
            float w = __expf(p - mh);
            sw += w;
            acc0 = fmaf(w, x0, acc0);
            acc1 = fmaf(w, x1, acc1);
        }
    }
    float inv = 1.f / (sw + 1e-16f);
    out[(size_t)warp * 40 + lane] = acc0 * inv + __ldg(&bias[lane]);
    if (has2) out[(size_t)warp * 40 + 32 + lane] = acc1 * inv + __ldg(&bias[32 + lane]);
}

// -------------------- launch --------------------------------------------------
extern "C" void kernel_launch(void* const* d_in, const int* in_sizes, int n_in,
                              void* d_out, int out_size) {
    const float* x     = (const float*)d_in[0];
    const int*   ei    = (const int*)d_in[1];   // edge_index int32, shape (2,E)
    const float* W0   = (const float*)d_in[2];  const float* b0   = (const float*)d_in[3];
    const float* W1l  = (const float*)d_in[4];  const float* b1l  = (const float*)d_in[5];
    const float* W1r  = (const float*)d_in[6];  const float* b1r  = (const float*)d_in[7];
    const float* att1 = (const float*)d_in[8];  const float* bias1= (const float*)d_in[9];
    const float* g1   = (const float*)d_in[10]; const float* be1  = (const float*)d_in[11];
    const float* W2l  = (const float*)d_in[12]; const float* b2l  = (const float*)d_in[13];
    const float* W2r  = (const float*)d_in[14]; const float* b2r  = (const float*)d_in[15];
    const float* att2 = (const float*)d_in[16]; const float* bias2= (const float*)d_in[17];
    const float* g2   = (const float*)d_in[18]; const float* be2  = (const float*)d_in[19];
    const float* W3l  = (const float*)d_in[20]; const float* b3l  = (const float*)d_in[21];
    const float* W3r  = (const float*)d_in[22]; const float* b3r  = (const float*)d_in[23];
    const float* att3 = (const float*)d_in[24]; const float* bias3= (const float*)d_in[25];
    float* out = (float*)d_out;

    float *xl, *xr, *idn, *x1, *x2;
    int *off, *cur, *srcs;
    cudaGetSymbolAddress((void**)&xl,   g_xl);
    cudaGetSymbolAddress((void**)&xr,   g_xr);
    cudaGetSymbolAddress((void**)&idn,  g_id);
    cudaGetSymbolAddress((void**)&x1,   g_x1);
    cudaGetSymbolAddress((void**)&x2,   g_x2);
    cudaGetSymbolAddress((void**)&off,  g_off);
    cudaGetSymbolAddress((void**)&cur,  g_cur);
    cudaGetSymbolAddress((void**)&srcs, g_srcs);

    const int N = NN, E = EE;
    int eblocks = (E + 255) / 256;
    int gatblocks = (N + 7) / 8;
    int nblocks = (N + 255) / 256;
    int mmblocks = (N + 63) / 64;

    // ---- CSR build ----
    zero_int_kernel<<<nblocks, 256>>>(cur, N);
    hist_kernel<<<eblocks, 256>>>(ei, E, cur);
    scan_kernel<<<1, 1024>>>(cur, off, N);
    copy_int_kernel<<<nblocks, 256>>>(off, cur, N);
    scatter_kernel<<<eblocks, 256>>>(ei, E, cur, srcs);

    // ---- identity + layer 1 ----
    gemm128_kernel<<<mmblocks, 256>>>(x, W0, b0, idn, N);
    gemm128_kernel<<<mmblocks, 256>>>(x, W1l, b1l, xl, N);
    gemm128_kernel<<<mmblocks, 256>>>(x, W1r, b1r, xr, N);
    gat_node128_kernel<<<gatblocks, 256>>>(xl, xr, off, srcs, att1, bias1, g1, be1, idn, x1, N);

    // ---- layer 2 ----
    gemm128_kernel<<<mmblocks, 256>>>(x1, W2l, b2l, xl, N);
    gemm128_kernel<<<mmblocks, 256>>>(x1, W2r, b2r, xr, N);
    gat_node128_kernel<<<gatblocks, 256>>>(xl, xr, off, srcs, att2, bias2, g2, be2, x1, x2, N);

    // ---- layer 3 (fused l/r narrow GEMM) ----
    gemm40x2_kernel<<<(N + 7) / 8, 128>>>(x2, W3l, b3l, W3r, b3r, xl, xr, N);
    gat_node40_kernel<<<gatblocks, 256>>>(xl, xr, off, srcs, att3, bias3, out, N);
}